// round 1
// baseline (speedup 1.0000x reference)
#include <cuda_runtime.h>

#define BB 16
#define NN 2048
#define DD 64
#define NT (NN / 64)   // 32 column tiles

// Scratch (device globals: allocation-free per harness rules).
// Q/K stored TRANSPOSED per batch: [b][d(64)][n(2048)] so the attention
// kernel stages k-major tiles into smem with coalesced loads and
// conflict-free (direct-copy) smem writes.
__device__ __align__(128) float g_Q[3][(size_t)BB * DD * NN];
__device__ __align__(128) float g_K[3][(size_t)BB * DD * NN];
__device__ __align__(128) float g_O[3][(size_t)BB * NN * DD];

__device__ __forceinline__ float ex2f(float x) {
    float y;
    asm("ex2.approx.ftz.f32 %0, %1;" : "=f"(y) : "f"(x));
    return y;
}

// ---------------------------------------------------------------------------
// Projection: Q_m = x_m @ W_m, K_m = x_m @ W_m^T, written d-major.
// Grid: (NT, B, 3), 256 threads.
// ---------------------------------------------------------------------------
__global__ void __launch_bounds__(256) proj_kernel(
    const float* __restrict__ x0, const float* __restrict__ x1,
    const float* __restrict__ x2, const float* __restrict__ W0,
    const float* __restrict__ W1, const float* __restrict__ W2)
{
    __shared__ float xs[64 * 65];   // xs[r*65+d], padded: (r+d) bank spread
    __shared__ float Ws[64 * 65];   // Ws[a*65+b] = W[a][b]

    const int m = blockIdx.z, b = blockIdx.y;
    const int row0 = blockIdx.x * 64;
    const float* x = (m == 0) ? x0 : ((m == 1) ? x1 : x2);
    const float* W = (m == 0) ? W0 : ((m == 1) ? W1 : W2);
    const int tid = threadIdx.x;

    const float* xg = x + ((size_t)b * NN + row0) * DD;
    for (int t = tid; t < 4096; t += 256) {
        int r = t >> 6, d = t & 63;
        xs[r * 65 + d] = xg[t];
        Ws[r * 65 + d] = W[t];      // here r plays the role of W's row index
    }
    __syncthreads();

    float* Qg = g_Q[m] + (size_t)b * DD * NN + row0;   // [e][n] slab
    float* Kg = g_K[m] + (size_t)b * DD * NN + row0;

    // t -> (e = t>>6, r = t&63): global writes coalesced over r (n-dim).
    for (int t = tid; t < 4096; t += 256) {
        int e = t >> 6, r = t & 63;
        float sq = 0.f, sk = 0.f;
        #pragma unroll 8
        for (int d = 0; d < 64; d++) {
            float xv = xs[r * 65 + d];         // lanes: r+d distinct banks
            sq = fmaf(xv, Ws[d * 65 + e], sq); // W[d][e] (broadcast e per warp)
            sk = fmaf(xv, Ws[e * 65 + d], sk); // W[e][d] (broadcast)
        }
        Qg[(size_t)e * NN + r] = sq;
        Kg[(size_t)e * NN + r] = sk;
    }
}

// ---------------------------------------------------------------------------
// Flash attention: CTA = (row-tile rt, batch b, query modality i).
// Loops j over the two partner modalities with independent online softmax.
// smem: Qs[k][r], Ks[k][c] (reused as Ps[m][r]), Vs[m][d] — 48 KB.
// ---------------------------------------------------------------------------
__global__ void __launch_bounds__(256, 2) attn_kernel(
    const float* __restrict__ x0, const float* __restrict__ x1,
    const float* __restrict__ x2)
{
    __shared__ __align__(16) float Qs[64 * 64];  // Qs[k*64 + r]
    __shared__ __align__(16) float Ks[64 * 64];  // Ks[k*64 + c]; reused as P[m*64 + r]
    __shared__ __align__(16) float Vs[64 * 64];  // Vs[m*64 + d]

    const int tid = threadIdx.x;
    const int tx = tid & 15, ty = tid >> 4;
    const int i = blockIdx.z, b = blockIdx.y;
    const int row0 = blockIdx.x * 64;
    const float* xp[3] = {x0, x1, x2};

    // Stage Q tile (k-major global -> direct smem copy, conflict-free)
    {
        const float* Qg = g_Q[i] + (size_t)b * DD * NN + row0;
        for (int t = tid; t < 4096; t += 256) {
            int k = t >> 6, r = t & 63;
            Qs[t] = Qg[(size_t)k * NN + r];
        }
    }

    float Oacc[4][4];
    #pragma unroll
    for (int a = 0; a < 4; a++)
        #pragma unroll
        for (int c = 0; c < 4; c++) Oacc[a][c] = 0.f;

    const float cf = 0.125f * 1.4426950408889634f;  // scale * log2(e)

    #pragma unroll
    for (int jj = 0; jj < 2; jj++) {
        const int j = (i + 1 + jj) % 3;
        const float* Kg = g_K[j] + (size_t)b * DD * NN;
        const float* Vg = xp[j] + (size_t)b * NN * DD;

        float Oj[4][4];
        float mrow[4], lrow[4];
        #pragma unroll
        for (int rr = 0; rr < 4; rr++) {
            mrow[rr] = -1e30f;
            lrow[rr] = 0.f;
            #pragma unroll
            for (int cc = 0; cc < 4; cc++) Oj[rr][cc] = 0.f;
        }

        for (int ct = 0; ct < NT; ct++) {
            __syncthreads();  // prior tile's P/V reads complete
            // Load K tile (k-major -> direct copy) and V tile (float4)
            {
                const float* Kt = Kg + ct * 64;
                for (int t = tid; t < 4096; t += 256) {
                    int k = t >> 6, c = t & 63;
                    Ks[t] = Kt[(size_t)k * NN + c];
                }
                const float4* Vt = (const float4*)(Vg + (size_t)ct * 64 * DD);
                for (int t = tid; t < 1024; t += 256)
                    ((float4*)Vs)[t] = Vt[t];
            }
            __syncthreads();

            // S = (Q K^T) * cf  — 4x4 register tile
            float S[4][4];
            #pragma unroll
            for (int rr = 0; rr < 4; rr++)
                #pragma unroll
                for (int cc = 0; cc < 4; cc++) S[rr][cc] = 0.f;

            #pragma unroll 8
            for (int k = 0; k < 64; k++) {
                const float4 q  = *(const float4*)(Qs + (k << 6) + (ty << 2));
                const float4 kv = *(const float4*)(Ks + (k << 6) + (tx << 2));
                S[0][0] = fmaf(q.x, kv.x, S[0][0]);
                S[0][1] = fmaf(q.x, kv.y, S[0][1]);
                S[0][2] = fmaf(q.x, kv.z, S[0][2]);
                S[0][3] = fmaf(q.x, kv.w, S[0][3]);
                S[1][0] = fmaf(q.y, kv.x, S[1][0]);
                S[1][1] = fmaf(q.y, kv.y, S[1][1]);
                S[1][2] = fmaf(q.y, kv.z, S[1][2]);
                S[1][3] = fmaf(q.y, kv.w, S[1][3]);
                S[2][0] = fmaf(q.z, kv.x, S[2][0]);
                S[2][1] = fmaf(q.z, kv.y, S[2][1]);
                S[2][2] = fmaf(q.z, kv.z, S[2][2]);
                S[2][3] = fmaf(q.z, kv.w, S[2][3]);
                S[3][0] = fmaf(q.w, kv.x, S[3][0]);
                S[3][1] = fmaf(q.w, kv.y, S[3][1]);
                S[3][2] = fmaf(q.w, kv.z, S[3][2]);
                S[3][3] = fmaf(q.w, kv.w, S[3][3]);
            }
            #pragma unroll
            for (int rr = 0; rr < 4; rr++)
                #pragma unroll
                for (int cc = 0; cc < 4; cc++) S[rr][cc] *= cf;

            // Online softmax per row (reduce across the 16 tx lanes)
            #pragma unroll
            for (int rr = 0; rr < 4; rr++) {
                float mx = fmaxf(fmaxf(S[rr][0], S[rr][1]),
                                 fmaxf(S[rr][2], S[rr][3]));
                mx = fmaxf(mx, __shfl_xor_sync(0xffffffffu, mx, 8));
                mx = fmaxf(mx, __shfl_xor_sync(0xffffffffu, mx, 4));
                mx = fmaxf(mx, __shfl_xor_sync(0xffffffffu, mx, 2));
                mx = fmaxf(mx, __shfl_xor_sync(0xffffffffu, mx, 1));
                const float mn = fmaxf(mrow[rr], mx);
                const float c = ex2f(mrow[rr] - mn);   // 0 on first tile
                mrow[rr] = mn;
                float rs = 0.f;
                #pragma unroll
                for (int cc = 0; cc < 4; cc++) {
                    float p = ex2f(S[rr][cc] - mn);
                    S[rr][cc] = p;
                    rs += p;
                }
                rs += __shfl_xor_sync(0xffffffffu, rs, 8);
                rs += __shfl_xor_sync(0xffffffffu, rs, 4);
                rs += __shfl_xor_sync(0xffffffffu, rs, 2);
                rs += __shfl_xor_sync(0xffffffffu, rs, 1);
                lrow[rr] = lrow[rr] * c + rs;
                #pragma unroll
                for (int cc = 0; cc < 4; cc++) Oj[rr][cc] *= c;
            }

            __syncthreads();  // all warps done reading Ks -> reuse as P
            // Store P transposed: Ps[m][r], m = 4*tx+cc, r = 4*ty..+3
            #pragma unroll
            for (int cc = 0; cc < 4; cc++) {
                float4 pv = make_float4(S[0][cc], S[1][cc], S[2][cc], S[3][cc]);
                *(float4*)(Ks + ((4 * tx + cc) << 6) + (ty << 2)) = pv;
            }
            __syncthreads();

            // O += P^T-staged GEMM: Oj[r][d] += sum_m P[m][r] * V[m][d]
            #pragma unroll 8
            for (int kk = 0; kk < 64; kk++) {
                const float4 p = *(const float4*)(Ks + (kk << 6) + (ty << 2));
                const float4 v = *(const float4*)(Vs + (kk << 6) + (tx << 2));
                Oj[0][0] = fmaf(p.x, v.x, Oj[0][0]);
                Oj[0][1] = fmaf(p.x, v.y, Oj[0][1]);
                Oj[0][2] = fmaf(p.x, v.z, Oj[0][2]);
                Oj[0][3] = fmaf(p.x, v.w, Oj[0][3]);
                Oj[1][0] = fmaf(p.y, v.x, Oj[1][0]);
                Oj[1][1] = fmaf(p.y, v.y, Oj[1][1]);
                Oj[1][2] = fmaf(p.y, v.z, Oj[1][2]);
                Oj[1][3] = fmaf(p.y, v.w, Oj[1][3]);
                Oj[2][0] = fmaf(p.z, v.x, Oj[2][0]);
                Oj[2][1] = fmaf(p.z, v.y, Oj[2][1]);
                Oj[2][2] = fmaf(p.z, v.z, Oj[2][2]);
                Oj[2][3] = fmaf(p.z, v.w, Oj[2][3]);
                Oj[3][0] = fmaf(p.w, v.x, Oj[3][0]);
                Oj[3][1] = fmaf(p.w, v.y, Oj[3][1]);
                Oj[3][2] = fmaf(p.w, v.z, Oj[3][2]);
                Oj[3][3] = fmaf(p.w, v.w, Oj[3][3]);
            }
        }

        #pragma unroll
        for (int rr = 0; rr < 4; rr++) {
            const float inv = 1.f / lrow[rr];
            #pragma unroll
            for (int cc = 0; cc < 4; cc++)
                Oacc[rr][cc] = fmaf(Oj[rr][cc], inv, Oacc[rr][cc]);
        }
    }

    // Write acc_i (pre-mean) to g_O[i]
    float* Og = g_O[i] + ((size_t)b * NN + row0) * DD;
    #pragma unroll
    for (int rr = 0; rr < 4; rr++) {
        float4 o = make_float4(Oacc[rr][0], Oacc[rr][1],
                               Oacc[rr][2], Oacc[rr][3]);
        *(float4*)(Og + ((4 * ty + rr) << 6) + (tx << 2)) = o;
    }
}

// ---------------------------------------------------------------------------
// out = (O0 + O1 + O2) / 3   (deterministic; avoids float atomics)
// ---------------------------------------------------------------------------
__global__ void __launch_bounds__(256) combine_kernel(float* __restrict__ out)
{
    const size_t t = (size_t)blockIdx.x * 256 + threadIdx.x;  // float4 index
    const float4 a = ((const float4*)g_O[0])[t];
    const float4 b = ((const float4*)g_O[1])[t];
    const float4 c = ((const float4*)g_O[2])[t];
    const float s = 1.f / 3.f;
    float4 o;
    o.x = (a.x + b.x + c.x) * s;
    o.y = (a.y + b.y + c.y) * s;
    o.z = (a.z + b.z + c.z) * s;
    o.w = (a.w + b.w + c.w) * s;
    ((float4*)out)[t] = o;
}

extern "C" void kernel_launch(void* const* d_in, const int* in_sizes, int n_in,
                              void* d_out, int out_size)
{
    const float* x0 = (const float*)d_in[0];  // x_rna
    const float* x1 = (const float*)d_in[1];  // x_cnv
    const float* x2 = (const float*)d_in[2];  // x_clinical
    const float* W0 = (const float*)d_in[3];  // W_rna
    const float* W1 = (const float*)d_in[4];  // W_cnv
    const float* W2 = (const float*)d_in[5];  // W_clinical
    float* out = (float*)d_out;

    proj_kernel<<<dim3(NT, BB, 3), 256>>>(x0, x1, x2, W0, W1, W2);
    attn_kernel<<<dim3(NT, BB, 3), 256>>>(x0, x1, x2);
    combine_kernel<<<(BB * NN * DD / 4) / 256, 256>>>(out);
}